// round 1
// baseline (speedup 1.0000x reference)
#include <cuda_runtime.h>
#include <cstdint>

#define BB 16
#define NPTS 2048
#define MM 16
#define SS 128
#define K2_BLOCKS ((BB * NPTS) / 256)

static __device__ float g_d1[BB * NPTS * MM];   // [b][n][m] min-over-s distance
static __device__ float g_colmean[BB * MM];     // mean over s of (clamped min-over-n)
static __device__ float g_part1[K2_BLOCKS];     // per-block partial sums of pcl_to_prim numerator

// ---------------------------------------------------------------------------
// Kernel 1: one CTA per (b,m). Computes, in a single pass over the 67M-element
// distance tensor slice (N x S per block):
//   - d1[b][n][m]   = min_s ||p_s - x_n||^2      (register min per thread)
//   - colmean[b][m] = mean_s min_n ||p_s - x_n||^2  (redux + smem atomicMin)
// dist = |p|^2 + |x|^2 - 2 p.x  -> 1 FADD + 3 FFMA per element.
// ---------------------------------------------------------------------------
__global__ __launch_bounds__(256) void k1(const float* __restrict__ pcl,
                                          const float* __restrict__ prim) {
    const int bm = blockIdx.x;
    const int b = bm >> 4;
    const int m = bm & 15;

    __shared__ float px[SS], py[SS], pz[SS], psq[SS];
    __shared__ unsigned smin[SS];
    __shared__ float red[256];

    const int tid = threadIdx.x;

    // Stage the S=128 primitive sample points for this (b,m).
    const float* pp = prim + (size_t)(b * MM + m) * SS * 3;
    for (int s = tid; s < SS; s += 256) {
        float a = pp[s * 3 + 0];
        float c = pp[s * 3 + 1];
        float d = pp[s * 3 + 2];
        px[s] = a; py[s] = c; pz[s] = d;
        psq[s] = a * a + c * c + d * d;
        smin[s] = 0x7f7fffffu;  // FLT_MAX bits (all dists are >= 0)
    }
    __syncthreads();

    // Each thread owns 8 pcl points: n = tid + k*256.
    float nx[8], ny[8], nz[8], uu[8], dmin[8];
#pragma unroll
    for (int k = 0; k < 8; k++) {
        int n = tid + k * 256;
        const float* xp = pcl + (((size_t)b * NPTS + n) * MM + m) * 3;
        float x = xp[0], y = xp[1], z = xp[2];
        nx[k] = -2.0f * x;
        ny[k] = -2.0f * y;
        nz[k] = -2.0f * z;
        uu[k] = x * x + y * y + z * z;
        dmin[k] = 3.4e38f;
    }

    for (int s = 0; s < SS; s++) {
        float a = px[s], c = py[s], d = pz[s], q = psq[s];
        float m8 = 3.4e38f;
#pragma unroll
        for (int k = 0; k < 8; k++) {
            float dist = q + uu[k];
            dist = fmaf(a, nx[k], dist);
            dist = fmaf(c, ny[k], dist);
            dist = fmaf(d, nz[k], dist);
            dist = fmaxf(dist, 0.0f);  // kill tiny negative from cancellation (keeps uint-min valid)
            dmin[k] = fminf(dmin[k], dist);
            m8 = fminf(m8, dist);
        }
        // min over the warp's 256 n-points for this s, one atomic per warp.
        unsigned u = __reduce_min_sync(0xffffffffu, __float_as_uint(m8));
        if ((tid & 31) == 0) atomicMin(&smin[s], u);
    }

    // Write d1 (min over s) for this thread's 8 points.
#pragma unroll
    for (int k = 0; k < 8; k++) {
        int n = tid + k * 256;
        g_d1[((size_t)b * NPTS + n) * MM + m] = dmin[k];
    }

    __syncthreads();

    // Deterministic block reduction of the S per-column mins -> mean over s.
    float v = 0.0f;
    if (tid < SS) {
        float f = __uint_as_float(smin[tid]);
        if (f >= 1e30f) f = 0.0f;  // INF_CLAMP rule
        v = f;
    }
    red[tid] = v;
    __syncthreads();
    for (int off = 64; off > 0; off >>= 1) {
        if (tid < off) red[tid] += red[tid + off];
        __syncthreads();
    }
    if (tid == 0) g_colmean[bm] = red[0] * (1.0f / SS);
}

// ---------------------------------------------------------------------------
// Kernel 2: per (b,n): sort the M=16 (dist, prob) pairs ascending by dist
// (odd-even transposition network, all compile-time indices -> registers),
// then stick-breaking weighted sum. Deterministic block-tree partials.
// ---------------------------------------------------------------------------
__global__ __launch_bounds__(256) void k2(const float* __restrict__ probs) {
    const int idx = blockIdx.x * 256 + threadIdx.x;  // < B*N
    const int b = idx / NPTS;

    float d[MM], p[MM];
    const float4* dp = (const float4*)(g_d1 + (size_t)idx * MM);
#pragma unroll
    for (int i = 0; i < 4; i++) {
        float4 v = dp[i];
        d[4 * i + 0] = v.x; d[4 * i + 1] = v.y;
        d[4 * i + 2] = v.z; d[4 * i + 3] = v.w;
    }
#pragma unroll
    for (int i = 0; i < MM; i++) p[i] = probs[b * MM + i];

    // Odd-even transposition sort, ascending by d.
#pragma unroll
    for (int r = 0; r < MM; r++) {
#pragma unroll
        for (int i = (r & 1); i + 1 < MM; i += 2) {
            if (d[i] > d[i + 1]) {
                float td = d[i]; d[i] = d[i + 1]; d[i + 1] = td;
                float tp = p[i]; p[i] = p[i + 1]; p[i + 1] = tp;
            }
        }
    }

    // sum_k d_(k) * p_(k) * prod_{j<k} (1 - p_(j))
    float run = 1.0f, sum = 0.0f;
#pragma unroll
    for (int i = 0; i < MM; i++) {
        sum += d[i] * p[i] * run;
        run *= (1.0f - p[i]);
    }

    __shared__ float red[256];
    red[threadIdx.x] = sum;
    __syncthreads();
    for (int off = 128; off > 0; off >>= 1) {
        if (threadIdx.x < off) red[threadIdx.x] += red[threadIdx.x + off];
        __syncthreads();
    }
    if (threadIdx.x == 0) g_part1[blockIdx.x] = red[0];
}

// ---------------------------------------------------------------------------
// Kernel 3: single block. Superquadric areas + per-b normalization, combine
// everything, write the 4 output scalars (total, pcl_to_prim, prim_to_pcl, 0).
// ---------------------------------------------------------------------------
__global__ __launch_bounds__(256) void k3(const float* __restrict__ size_,
                                          const float* __restrict__ probs,
                                          float* __restrict__ out, int out_size) {
    const int tid = threadIdx.x;  // 256 == B*M
    const float FOUR_PI = 12.566370614359172f;

    __shared__ float area[256];
    __shared__ float red[256];
    __shared__ float p1_shared;

    const int b = tid >> 4;

    float s0 = size_[tid * 3 + 0];
    float s1 = size_[tid * 3 + 1];
    float s2 = size_[tid * 3 + 2];
    float inner = (powf(s0 * s1, 1.6f) + powf(s0 * s2, 1.6f) + powf(s1 * s2, 1.6f)) * (1.0f / 3.0f);
    float ar = FOUR_PI * powf(inner, 0.625f);
    area[tid] = ar;
    __syncthreads();

    float sb = 0.0f;
#pragma unroll
    for (int j = 0; j < MM; j++) sb += area[b * MM + j];

    float contrib = g_colmean[tid] * probs[tid] * ((float)MM * ar / sb) * (1.0f / (BB * MM));

    // Reduce pcl_to_prim partials (128 of them).
    red[tid] = (tid < K2_BLOCKS) ? g_part1[tid] : 0.0f;
    __syncthreads();
    for (int off = 128; off > 0; off >>= 1) {
        if (tid < off) red[tid] += red[tid + off];
        __syncthreads();
    }
    if (tid == 0) p1_shared = red[0];
    __syncthreads();

    // Reduce prim_to_pcl contributions.
    red[tid] = contrib;
    __syncthreads();
    for (int off = 128; off > 0; off >>= 1) {
        if (tid < off) red[tid] += red[tid + off];
        __syncthreads();
    }

    if (tid == 0) {
        float pcl_to_prim = p1_shared * (1.0f / ((float)BB * (float)NPTS));
        float prim_to_pcl = red[0];
        float total = pcl_to_prim + prim_to_pcl;
        if (out_size > 0) out[0] = total;
        if (out_size > 1) out[1] = pcl_to_prim;
        if (out_size > 2) out[2] = prim_to_pcl;
        if (out_size > 3) out[3] = 0.0f;
    }
}

extern "C" void kernel_launch(void* const* d_in, const int* in_sizes, int n_in,
                              void* d_out, int out_size) {
    const float* pcl   = (const float*)d_in[0];  // (B, N, M, 3)
    const float* prim  = (const float*)d_in[1];  // (B, M, S, 3)
    const float* size_ = (const float*)d_in[2];  // (B, M, 3)
    const float* probs = (const float*)d_in[3];  // (B, M)

    k1<<<BB * MM, 256>>>(pcl, prim);
    k2<<<K2_BLOCKS, 256>>>(probs);
    k3<<<1, 256>>>(size_, probs, (float*)d_out, out_size);
}